// round 1
// baseline (speedup 1.0000x reference)
#include <cuda_runtime.h>
#include <math.h>

#define TOKENS  2048
#define HIDDEN  2048
#define INTER   5632
#define NEXPERTS 8
#define TOPK    2
#define NSLOTS  (TOKENS * TOPK)

#define BM 64
#define BN 64
#define BK 16

// Scratch (static device allocations — allowed)
__device__ int   g_counts[NEXPERTS];
__device__ int   g_slots[NEXPERTS * NSLOTS];
__device__ float g_h[(size_t)NSLOTS * INTER];    // gated hidden, per slot
__device__ float g_y[(size_t)NSLOTS * HIDDEN];   // per-slot expert output

__global__ void zero_counts_kernel() {
    if (threadIdx.x < NEXPERTS) g_counts[threadIdx.x] = 0;
}

__global__ void route_kernel(const int* __restrict__ idx) {
    int s = blockIdx.x * blockDim.x + threadIdx.x;
    if (s >= NSLOTS) return;
    int e = idx[s];
    int pos = atomicAdd(&g_counts[e], 1);
    g_slots[e * NSLOTS + pos] = s;
}

// Stage 1: for expert e, rows = gathered tokens, compute
//   h[slot, i] = silu(x@w1) * (x@w3), both GEMMs fused (shared A tile).
__global__ __launch_bounds__(256, 2)
void ffn1_kernel(const float* __restrict__ x,
                 const float* __restrict__ w1,
                 const float* __restrict__ w3) {
    int e = blockIdx.z;
    int count = g_counts[e];
    int row0 = blockIdx.y * BM;
    if (row0 >= count) return;
    int col0 = blockIdx.x * BN;

    __shared__ float As[BM][BK];
    __shared__ float B1s[BK][BN];
    __shared__ float B3s[BK][BN];

    int tid = threadIdx.x;
    int tx = tid & 15;          // output col group
    int ty = tid >> 4;          // output row group

    // loader mapping
    int lar = tid >> 2;         // A row 0..63
    int lac = (tid & 3) * 4;    // A col {0,4,8,12}
    int lbr = tid >> 4;         // B row 0..15
    int lbc = (tid & 15) * 4;   // B col {0..60}

    int arow = row0 + lar;
    int atok = -1;
    if (arow < count) atok = g_slots[e * NSLOTS + arow] >> 1;  // token id

    const float* w1p = w1 + (size_t)e * HIDDEN * INTER;
    const float* w3p = w3 + (size_t)e * HIDDEN * INTER;

    float acc1[4][4];
    float acc3[4][4];
    #pragma unroll
    for (int i = 0; i < 4; i++)
        #pragma unroll
        for (int j = 0; j < 4; j++) { acc1[i][j] = 0.f; acc3[i][j] = 0.f; }

    for (int k0 = 0; k0 < HIDDEN; k0 += BK) {
        float4 av = make_float4(0.f, 0.f, 0.f, 0.f);
        if (atok >= 0)
            av = *(const float4*)(x + (size_t)atok * HIDDEN + k0 + lac);
        *(float4*)&As[lar][lac] = av;

        float4 b1v = *(const float4*)(w1p + (size_t)(k0 + lbr) * INTER + col0 + lbc);
        float4 b3v = *(const float4*)(w3p + (size_t)(k0 + lbr) * INTER + col0 + lbc);
        *(float4*)&B1s[lbr][lbc] = b1v;
        *(float4*)&B3s[lbr][lbc] = b3v;
        __syncthreads();

        #pragma unroll
        for (int kk = 0; kk < BK; kk++) {
            float a[4];
            #pragma unroll
            for (int i = 0; i < 4; i++) a[i] = As[ty * 4 + i][kk];
            float4 b1 = *(float4*)&B1s[kk][tx * 4];
            float4 b3 = *(float4*)&B3s[kk][tx * 4];
            #pragma unroll
            for (int i = 0; i < 4; i++) {
                acc1[i][0] += a[i] * b1.x;
                acc1[i][1] += a[i] * b1.y;
                acc1[i][2] += a[i] * b1.z;
                acc1[i][3] += a[i] * b1.w;
                acc3[i][0] += a[i] * b3.x;
                acc3[i][1] += a[i] * b3.y;
                acc3[i][2] += a[i] * b3.z;
                acc3[i][3] += a[i] * b3.w;
            }
        }
        __syncthreads();
    }

    // Epilogue: h = silu(gate) * up, scatter to per-slot buffer
    #pragma unroll
    for (int i = 0; i < 4; i++) {
        int r = row0 + ty * 4 + i;
        if (r >= count) continue;
        int s = g_slots[e * NSLOTS + r];
        float4 hv;
        float g, u;
        g = acc1[i][0]; u = acc3[i][0]; hv.x = (g / (1.f + expf(-g))) * u;
        g = acc1[i][1]; u = acc3[i][1]; hv.y = (g / (1.f + expf(-g))) * u;
        g = acc1[i][2]; u = acc3[i][2]; hv.z = (g / (1.f + expf(-g))) * u;
        g = acc1[i][3]; u = acc3[i][3]; hv.w = (g / (1.f + expf(-g))) * u;
        *(float4*)(g_h + (size_t)s * INTER + col0 + tx * 4) = hv;
    }
}

// Stage 2: y[slot, :] = h[slot, :] @ w2[e]
__global__ __launch_bounds__(256, 2)
void ffn2_kernel(const float* __restrict__ w2) {
    int e = blockIdx.z;
    int count = g_counts[e];
    int row0 = blockIdx.y * BM;
    if (row0 >= count) return;
    int col0 = blockIdx.x * BN;

    __shared__ float As[BM][BK];
    __shared__ float Bs[BK][BN];

    int tid = threadIdx.x;
    int tx = tid & 15;
    int ty = tid >> 4;

    int lar = tid >> 2;
    int lac = (tid & 3) * 4;
    int lbr = tid >> 4;
    int lbc = (tid & 15) * 4;

    int arow = row0 + lar;
    int aslot = -1;
    if (arow < count) aslot = g_slots[e * NSLOTS + arow];

    const float* w2p = w2 + (size_t)e * INTER * HIDDEN;

    float acc[4][4];
    #pragma unroll
    for (int i = 0; i < 4; i++)
        #pragma unroll
        for (int j = 0; j < 4; j++) acc[i][j] = 0.f;

    for (int k0 = 0; k0 < INTER; k0 += BK) {
        float4 av = make_float4(0.f, 0.f, 0.f, 0.f);
        if (aslot >= 0)
            av = *(const float4*)(g_h + (size_t)aslot * INTER + k0 + lac);
        *(float4*)&As[lar][lac] = av;

        float4 bv = *(const float4*)(w2p + (size_t)(k0 + lbr) * HIDDEN + col0 + lbc);
        *(float4*)&Bs[lbr][lbc] = bv;
        __syncthreads();

        #pragma unroll
        for (int kk = 0; kk < BK; kk++) {
            float a[4];
            #pragma unroll
            for (int i = 0; i < 4; i++) a[i] = As[ty * 4 + i][kk];
            float4 b = *(float4*)&Bs[kk][tx * 4];
            #pragma unroll
            for (int i = 0; i < 4; i++) {
                acc[i][0] += a[i] * b.x;
                acc[i][1] += a[i] * b.y;
                acc[i][2] += a[i] * b.z;
                acc[i][3] += a[i] * b.w;
            }
        }
        __syncthreads();
    }

    #pragma unroll
    for (int i = 0; i < 4; i++) {
        int r = row0 + ty * 4 + i;
        if (r >= count) continue;
        int s = g_slots[e * NSLOTS + r];
        float4 yv = make_float4(acc[i][0], acc[i][1], acc[i][2], acc[i][3]);
        *(float4*)(g_y + (size_t)s * HIDDEN + col0 + tx * 4) = yv;
    }
}

// Combine: out[t] = ew[t,0]*y[2t] + ew[t,1]*y[2t+1]
__global__ void combine_kernel(const float* __restrict__ ew,
                               float* __restrict__ out) {
    int i = blockIdx.x * blockDim.x + threadIdx.x;
    const int n4 = TOKENS * HIDDEN / 4;
    if (i >= n4) return;
    int t  = i / (HIDDEN / 4);
    int c4 = (i % (HIDDEN / 4)) * 4;
    float w0 = ew[t * 2 + 0];
    float w1v = ew[t * 2 + 1];
    float4 y0 = *(const float4*)(g_y + (size_t)(2 * t + 0) * HIDDEN + c4);
    float4 y1 = *(const float4*)(g_y + (size_t)(2 * t + 1) * HIDDEN + c4);
    float4 o;
    o.x = w0 * y0.x + w1v * y1.x;
    o.y = w0 * y0.y + w1v * y1.y;
    o.z = w0 * y0.z + w1v * y1.z;
    o.w = w0 * y0.w + w1v * y1.w;
    *(float4*)(out + (size_t)t * HIDDEN + c4) = o;
}

extern "C" void kernel_launch(void* const* d_in, const int* in_sizes, int n_in,
                              void* d_out, int out_size) {
    const float* x   = (const float*)d_in[0];
    const float* ew  = (const float*)d_in[1];
    const float* w1  = (const float*)d_in[2];
    const float* w2  = (const float*)d_in[3];
    const float* w3  = (const float*)d_in[4];
    const int*   idx = (const int*)d_in[5];
    float* out = (float*)d_out;

    zero_counts_kernel<<<1, 32>>>();
    route_kernel<<<NSLOTS / 256, 256>>>(idx);

    dim3 g1(INTER / BN, NSLOTS / BM, NEXPERTS);
    ffn1_kernel<<<g1, 256>>>(x, w1, w3);

    dim3 g2(HIDDEN / BN, NSLOTS / BM, NEXPERTS);
    ffn2_kernel<<<g2, 256>>>(w2);

    combine_kernel<<<(TOKENS * HIDDEN / 4 + 255) / 256, 256>>>(ew, out);
}

// round 3
// speedup vs baseline: 4.2006x; 4.2006x over previous
#include <cuda_runtime.h>
#include <math.h>
#include <cstdint>

#define TOKENS  2048
#define HIDDEN  2048
#define INTER   5632
#define NEXPERTS 8
#define TOPK    2
#define NSLOTS  (TOKENS * TOPK)
#define BK 32

// ---------------- scratch ----------------
__device__ int   g_counts[NEXPERTS];
__device__ int   g_slots[NEXPERTS * NSLOTS];
__device__ float g_x[(size_t)TOKENS * HIDDEN];   // tf32-rounded x
__device__ float g_h[(size_t)NSLOTS * INTER];    // tf32-rounded hidden
__device__ float g_y[(size_t)NSLOTS * HIDDEN];

// ---------------- helpers ----------------
__device__ __forceinline__ uint32_t smem_u32(const void* p) {
    uint32_t a;
    asm("{ .reg .u64 t; cvta.to.shared.u64 t, %1; cvt.u32.u64 %0, t; }" : "=r"(a) : "l"(p));
    return a;
}
__device__ __forceinline__ uint32_t f2tf32(float f) {
    uint32_t r;
    asm("cvt.rna.tf32.f32 %0, %1;" : "=r"(r) : "f"(f));
    return r;
}
__device__ __forceinline__ void cp16(uint32_t dst, const void* src, int sz) {
    asm volatile("cp.async.cg.shared.global [%0], [%1], 16, %2;"
                 :: "r"(dst), "l"(src), "r"(sz) : "memory");
}
#define CP_COMMIT() asm volatile("cp.async.commit_group;" ::: "memory")
#define CP_WAIT0()  asm volatile("cp.async.wait_group 0;" ::: "memory")

__device__ __forceinline__ void mma8(float& d0, float& d1, float& d2, float& d3,
                                     uint32_t a0, uint32_t a1, uint32_t a2, uint32_t a3,
                                     uint32_t b0, uint32_t b1) {
    asm volatile(
        "mma.sync.aligned.m16n8k8.row.col.f32.tf32.tf32.f32 "
        "{%0,%1,%2,%3},{%4,%5,%6,%7},{%8,%9},{%0,%1,%2,%3};"
        : "+f"(d0), "+f"(d1), "+f"(d2), "+f"(d3)
        : "r"(a0), "r"(a1), "r"(a2), "r"(a3), "r"(b0), "r"(b1));
}
__device__ __forceinline__ float silu(float g) { return g / (1.f + expf(-g)); }

// ---------------- small kernels ----------------
__global__ void zero_counts_kernel() {
    if (threadIdx.x < NEXPERTS) g_counts[threadIdx.x] = 0;
}
__global__ void route_kernel(const int* __restrict__ idx) {
    int s = blockIdx.x * blockDim.x + threadIdx.x;
    if (s >= NSLOTS) return;
    int e = idx[s];
    int pos = atomicAdd(&g_counts[e], 1);
    g_slots[e * NSLOTS + pos] = s;
}
__global__ void round_x_kernel(const float* __restrict__ x) {
    int i = blockIdx.x * blockDim.x + threadIdx.x;
    if (i >= TOKENS * HIDDEN / 4) return;
    float4 v = *(const float4*)(x + i * 4);
    float4 o;
    o.x = __uint_as_float(f2tf32(v.x));
    o.y = __uint_as_float(f2tf32(v.y));
    o.z = __uint_as_float(f2tf32(v.z));
    o.w = __uint_as_float(f2tf32(v.w));
    *(float4*)(g_x + i * 4) = o;
}

// ================= stage 1 =================
// CTA: 128 rows x 64 inter-cols, gate+up fused. 8 warps (4m x 2n), warp 32x32 each.
// smem bytes: A0@0 A1@16384 | B1a@32768 B1b@41984 | B3a@51200 B3b@60416 | rows@69632
#define S1_SMEM 70144
extern __shared__ char smem[];

__global__ __launch_bounds__(256, 2)
void ffn1_mma(const float* __restrict__ w1, const float* __restrict__ w3) {
    const int e = blockIdx.z;
    const int count = g_counts[e];
    const int row0 = blockIdx.x * 128;
    if (row0 >= count) return;
    const int colbase = blockIdx.y * 64;

    const int tid = threadIdx.x;
    const int lane = tid & 31;
    const int wid = tid >> 5;
    const int q = lane & 3, gid = lane >> 2;
    const int warpm = wid >> 1, warpn = wid & 1;

    int* rowsS = (int*)(smem + 69632);
    if (tid < 128) {
        int r = row0 + tid;
        rowsS[tid] = (r < count) ? g_slots[e * NSLOTS + r] : -1;
    }
    __syncthreads();

    const uint32_t sb = smem_u32(smem);
    const float* w1p = w1 + (size_t)e * HIDDEN * INTER + colbase;
    const float* w3p = w3 + (size_t)e * HIDDEN * INTER + colbase;

    float ag[2][4][4], au[2][4][4];
    #pragma unroll
    for (int i = 0; i < 2; i++)
        #pragma unroll
        for (int j = 0; j < 4; j++)
            #pragma unroll
            for (int k = 0; k < 4; k++) { ag[i][j][k] = 0.f; au[i][j][k] = 0.f; }

    float4 r1[2], r3[2];

    // ---- prologue: chunk 0 ----
    #pragma unroll
    for (int p = 0; p < 2; p++) {
        int t = tid + p * 256;
        int k = t >> 4, u = t & 15;
        r1[p] = *(const float4*)(w1p + (size_t)k * INTER + u * 4);
        r3[p] = *(const float4*)(w3p + (size_t)k * INTER + u * 4);
    }
    #pragma unroll
    for (int p = 0; p < 4; p++) {
        int t = tid + p * 256;
        int r = t >> 3, g = t & 7;
        int slot = rowsS[r];
        uint32_t dst = sb + r * 128 + ((g ^ (r & 7)) << 4);
        cp16(dst, g_x + (size_t)(slot >> 1) * HIDDEN + g * 4, slot >= 0 ? 16 : 0);
    }
    CP_COMMIT();
    #pragma unroll
    for (int p = 0; p < 2; p++) {
        int t = tid + p * 256;
        int k = t >> 4, u = t & 15;
        uint32_t* d1 = (uint32_t*)(smem + 32768) + k * 72 + u * 4;
        uint32_t* d3 = (uint32_t*)(smem + 51200) + k * 72 + u * 4;
        d1[0] = f2tf32(r1[p].x); d1[1] = f2tf32(r1[p].y); d1[2] = f2tf32(r1[p].z); d1[3] = f2tf32(r1[p].w);
        d3[0] = f2tf32(r3[p].x); d3[1] = f2tf32(r3[p].y); d3[2] = f2tf32(r3[p].z); d3[3] = f2tf32(r3[p].w);
    }
    CP_WAIT0();
    __syncthreads();

    const int NCH = HIDDEN / BK;  // 64
    for (int i = 0; i < NCH; i++) {
        int cur = i & 1, nxt = cur ^ 1;
        int k0n = (i + 1) * BK;
        // prefetch next
        if (i + 1 < NCH) {
            #pragma unroll
            for (int p = 0; p < 2; p++) {
                int t = tid + p * 256;
                int k = t >> 4, u = t & 15;
                r1[p] = *(const float4*)(w1p + (size_t)(k0n + k) * INTER + u * 4);
                r3[p] = *(const float4*)(w3p + (size_t)(k0n + k) * INTER + u * 4);
            }
            #pragma unroll
            for (int p = 0; p < 4; p++) {
                int t = tid + p * 256;
                int r = t >> 3, g = t & 7;
                int slot = rowsS[r];
                uint32_t dst = sb + nxt * 16384 + r * 128 + ((g ^ (r & 7)) << 4);
                cp16(dst, g_x + (size_t)(slot >> 1) * HIDDEN + k0n + g * 4, slot >= 0 ? 16 : 0);
            }
            CP_COMMIT();
        }
        // mma on cur
        const uint32_t* As = (const uint32_t*)(smem + cur * 16384);
        const uint32_t* B1 = (const uint32_t*)(smem + 32768 + cur * 9216);
        const uint32_t* B3 = (const uint32_t*)(smem + 51200 + cur * 9216);
        #pragma unroll
        for (int ks = 0; ks < 4; ks++) {
            uint32_t a[2][4];
            int g0 = (((2 * ks) ^ gid) << 2) + q;
            int g1 = (((2 * ks + 1) ^ gid) << 2) + q;
            #pragma unroll
            for (int mt = 0; mt < 2; mt++) {
                int rb = warpm * 32 + mt * 16 + gid;
                a[mt][0] = As[rb * 32 + g0];
                a[mt][1] = As[(rb + 8) * 32 + g0];
                a[mt][2] = As[rb * 32 + g1];
                a[mt][3] = As[(rb + 8) * 32 + g1];
            }
            int kr0 = (ks * 8 + q) * 72, kr1 = (ks * 8 + q + 4) * 72;
            #pragma unroll
            for (int nt = 0; nt < 4; nt++) {
                int nb = warpn * 32 + nt * 8 + gid;
                uint32_t b0 = B1[kr0 + nb], b1 = B1[kr1 + nb];
                mma8(ag[0][nt][0], ag[0][nt][1], ag[0][nt][2], ag[0][nt][3],
                     a[0][0], a[0][1], a[0][2], a[0][3], b0, b1);
                mma8(ag[1][nt][0], ag[1][nt][1], ag[1][nt][2], ag[1][nt][3],
                     a[1][0], a[1][1], a[1][2], a[1][3], b0, b1);
                uint32_t c0 = B3[kr0 + nb], c1 = B3[kr1 + nb];
                mma8(au[0][nt][0], au[0][nt][1], au[0][nt][2], au[0][nt][3],
                     a[0][0], a[0][1], a[0][2], a[0][3], c0, c1);
                mma8(au[1][nt][0], au[1][nt][1], au[1][nt][2], au[1][nt][3],
                     a[1][0], a[1][1], a[1][2], a[1][3], c0, c1);
            }
        }
        // stage next B into smem
        if (i + 1 < NCH) {
            #pragma unroll
            for (int p = 0; p < 2; p++) {
                int t = tid + p * 256;
                int k = t >> 4, u = t & 15;
                uint32_t* d1 = (uint32_t*)(smem + 32768 + nxt * 9216) + k * 72 + u * 4;
                uint32_t* d3 = (uint32_t*)(smem + 51200 + nxt * 9216) + k * 72 + u * 4;
                d1[0] = f2tf32(r1[p].x); d1[1] = f2tf32(r1[p].y); d1[2] = f2tf32(r1[p].z); d1[3] = f2tf32(r1[p].w);
                d3[0] = f2tf32(r3[p].x); d3[1] = f2tf32(r3[p].y); d3[2] = f2tf32(r3[p].z); d3[3] = f2tf32(r3[p].w);
            }
        }
        CP_WAIT0();
        __syncthreads();
    }

    // ---- epilogue: silu(gate)*up, round to tf32, scatter ----
    #pragma unroll
    for (int mt = 0; mt < 2; mt++) {
        #pragma unroll
        for (int half = 0; half < 2; half++) {
            int r = warpm * 32 + mt * 16 + gid + half * 8;
            int slot = rowsS[r];
            if (slot < 0) continue;
            float* dst = g_h + (size_t)slot * INTER + colbase + warpn * 32;
            #pragma unroll
            for (int nt = 0; nt < 4; nt++) {
                float gg0 = ag[mt][nt][half * 2 + 0], uu0 = au[mt][nt][half * 2 + 0];
                float gg1 = ag[mt][nt][half * 2 + 1], uu1 = au[mt][nt][half * 2 + 1];
                float2 o;
                o.x = __uint_as_float(f2tf32(silu(gg0) * uu0));
                o.y = __uint_as_float(f2tf32(silu(gg1) * uu1));
                *(float2*)(dst + nt * 8 + 2 * q) = o;
            }
        }
    }
}

// ================= stage 2 =================
// CTA: 128 rows x 128 cols. 8 warps (4m x 2n), warp tile 32x64.
// smem: A0@0 A1@16384 | B0@32768 B1@50176 | rows@67584
#define S2_SMEM 68096

__global__ __launch_bounds__(256, 2)
void ffn2_mma(const float* __restrict__ w2) {
    const int e = blockIdx.z;
    const int count = g_counts[e];
    const int row0 = blockIdx.x * 128;
    if (row0 >= count) return;
    const int colbase = blockIdx.y * 128;

    const int tid = threadIdx.x;
    const int lane = tid & 31;
    const int wid = tid >> 5;
    const int q = lane & 3, gid = lane >> 2;
    const int warpm = wid >> 1, warpn = wid & 1;

    int* rowsS = (int*)(smem + 67584);
    if (tid < 128) {
        int r = row0 + tid;
        rowsS[tid] = (r < count) ? g_slots[e * NSLOTS + r] : -1;
    }
    __syncthreads();

    const uint32_t sb = smem_u32(smem);
    const float* w2p = w2 + (size_t)e * INTER * HIDDEN + colbase;

    float acc[2][8][4];
    #pragma unroll
    for (int i = 0; i < 2; i++)
        #pragma unroll
        for (int j = 0; j < 8; j++)
            #pragma unroll
            for (int k = 0; k < 4; k++) acc[i][j][k] = 0.f;

    float4 rb[4];

    #pragma unroll
    for (int p = 0; p < 4; p++) {
        int t = tid + p * 256;
        int k = t >> 5, u = t & 31;
        rb[p] = *(const float4*)(w2p + (size_t)k * HIDDEN + u * 4);
    }
    #pragma unroll
    for (int p = 0; p < 4; p++) {
        int t = tid + p * 256;
        int r = t >> 3, g = t & 7;
        int slot = rowsS[r];
        uint32_t dst = sb + r * 128 + ((g ^ (r & 7)) << 4);
        cp16(dst, g_h + (size_t)slot * INTER + g * 4, slot >= 0 ? 16 : 0);
    }
    CP_COMMIT();
    #pragma unroll
    for (int p = 0; p < 4; p++) {
        int t = tid + p * 256;
        int k = t >> 5, u = t & 31;
        uint32_t* d = (uint32_t*)(smem + 32768) + k * 136 + u * 4;
        d[0] = f2tf32(rb[p].x); d[1] = f2tf32(rb[p].y); d[2] = f2tf32(rb[p].z); d[3] = f2tf32(rb[p].w);
    }
    CP_WAIT0();
    __syncthreads();

    const int NCH = INTER / BK;  // 176
    for (int i = 0; i < NCH; i++) {
        int cur = i & 1, nxt = cur ^ 1;
        int k0n = (i + 1) * BK;
        if (i + 1 < NCH) {
            #pragma unroll
            for (int p = 0; p < 4; p++) {
                int t = tid + p * 256;
                int k = t >> 5, u = t & 31;
                rb[p] = *(const float4*)(w2p + (size_t)(k0n + k) * HIDDEN + u * 4);
            }
            #pragma unroll
            for (int p = 0; p < 4; p++) {
                int t = tid + p * 256;
                int r = t >> 3, g = t & 7;
                int slot = rowsS[r];
                uint32_t dst = sb + nxt * 16384 + r * 128 + ((g ^ (r & 7)) << 4);
                cp16(dst, g_h + (size_t)slot * INTER + k0n + g * 4, slot >= 0 ? 16 : 0);
            }
            CP_COMMIT();
        }
        const uint32_t* As = (const uint32_t*)(smem + cur * 16384);
        const uint32_t* Bs = (const uint32_t*)(smem + 32768 + cur * 17408);
        #pragma unroll
        for (int ks = 0; ks < 4; ks++) {
            uint32_t a[2][4];
            int g0 = (((2 * ks) ^ gid) << 2) + q;
            int g1 = (((2 * ks + 1) ^ gid) << 2) + q;
            #pragma unroll
            for (int mt = 0; mt < 2; mt++) {
                int rbs = warpm * 32 + mt * 16 + gid;
                a[mt][0] = As[rbs * 32 + g0];
                a[mt][1] = As[(rbs + 8) * 32 + g0];
                a[mt][2] = As[rbs * 32 + g1];
                a[mt][3] = As[(rbs + 8) * 32 + g1];
            }
            int kr0 = (ks * 8 + q) * 136, kr1 = (ks * 8 + q + 4) * 136;
            #pragma unroll
            for (int nt = 0; nt < 8; nt++) {
                int nb = warpn * 64 + nt * 8 + gid;
                uint32_t b0 = Bs[kr0 + nb], b1 = Bs[kr1 + nb];
                mma8(acc[0][nt][0], acc[0][nt][1], acc[0][nt][2], acc[0][nt][3],
                     a[0][0], a[0][1], a[0][2], a[0][3], b0, b1);
                mma8(acc[1][nt][0], acc[1][nt][1], acc[1][nt][2], acc[1][nt][3],
                     a[1][0], a[1][1], a[1][2], a[1][3], b0, b1);
            }
        }
        if (i + 1 < NCH) {
            #pragma unroll
            for (int p = 0; p < 4; p++) {
                int t = tid + p * 256;
                int k = t >> 5, u = t & 31;
                uint32_t* d = (uint32_t*)(smem + 32768 + nxt * 17408) + k * 136 + u * 4;
                d[0] = f2tf32(rb[p].x); d[1] = f2tf32(rb[p].y); d[2] = f2tf32(rb[p].z); d[3] = f2tf32(rb[p].w);
            }
        }
        CP_WAIT0();
        __syncthreads();
    }

    #pragma unroll
    for (int mt = 0; mt < 2; mt++) {
        #pragma unroll
        for (int half = 0; half < 2; half++) {
            int r = warpm * 32 + mt * 16 + gid + half * 8;
            int slot = rowsS[r];
            if (slot < 0) continue;
            float* dst = g_y + (size_t)slot * HIDDEN + colbase + warpn * 64;
            #pragma unroll
            for (int nt = 0; nt < 8; nt++) {
                float2 o;
                o.x = acc[mt][nt][half * 2 + 0];
                o.y = acc[mt][nt][half * 2 + 1];
                *(float2*)(dst + nt * 8 + 2 * q) = o;
            }
        }
    }
}

// ---------------- combine ----------------
__global__ void combine_kernel(const float* __restrict__ ew,
                               float* __restrict__ out) {
    int i = blockIdx.x * blockDim.x + threadIdx.x;
    const int n4 = TOKENS * HIDDEN / 4;
    if (i >= n4) return;
    int t  = i / (HIDDEN / 4);
    int c4 = (i % (HIDDEN / 4)) * 4;
    float w0 = ew[t * 2 + 0];
    float w1v = ew[t * 2 + 1];
    float4 y0 = *(const float4*)(g_y + (size_t)(2 * t + 0) * HIDDEN + c4);
    float4 y1 = *(const float4*)(g_y + (size_t)(2 * t + 1) * HIDDEN + c4);
    float4 o;
    o.x = w0 * y0.x + w1v * y1.x;
    o.y = w0 * y0.y + w1v * y1.y;
    o.z = w0 * y0.z + w1v * y1.z;
    o.w = w0 * y0.w + w1v * y1.w;
    *(float4*)(out + (size_t)t * HIDDEN + c4) = o;
}

// ---------------- launch ----------------
extern "C" void kernel_launch(void* const* d_in, const int* in_sizes, int n_in,
                              void* d_out, int out_size) {
    const float* x   = (const float*)d_in[0];
    const float* ew  = (const float*)d_in[1];
    const float* w1  = (const float*)d_in[2];
    const float* w2  = (const float*)d_in[3];
    const float* w3  = (const float*)d_in[4];
    const int*   idx = (const int*)d_in[5];
    float* out = (float*)d_out;

    cudaFuncSetAttribute(ffn1_mma, cudaFuncAttributeMaxDynamicSharedMemorySize, S1_SMEM);
    cudaFuncSetAttribute(ffn2_mma, cudaFuncAttributeMaxDynamicSharedMemorySize, S2_SMEM);

    zero_counts_kernel<<<1, 32>>>();
    route_kernel<<<NSLOTS / 256, 256>>>(idx);
    round_x_kernel<<<(TOKENS * HIDDEN / 4 + 255) / 256, 256>>>(x);

    dim3 g1(NSLOTS / 128, INTER / 64, NEXPERTS);    // mtile fastest
    ffn1_mma<<<g1, 256, S1_SMEM>>>(w1, w3);

    dim3 g2(NSLOTS / 128, HIDDEN / 128, NEXPERTS);
    ffn2_mma<<<g2, 256, S2_SMEM>>>(w2);

    combine_kernel<<<(TOKENS * HIDDEN / 4 + 255) / 256, 256>>>(ew, out);
}